// round 8
// baseline (speedup 1.0000x reference)
#include <cuda_runtime.h>
#include <cuda_bf16.h>
#include <cstdint>

#define D 128
#define K 64
#define TILE 128
#define NT_MAX 1563
#define NB 148
#define TEMP 30.0f
#define EPSn 1e-6f
#define ITERS 11

// smem byte offsets
#define OFF_MU 0                 // MuH 16KB | MuL 16KB
#define OFF_X  32768             // buf0: Xh 32K | Xl 32K ; buf1 at +65536
#define OFF_R  163840            // Rh 16K | Rl 16K
#define OFF_CNT 196608           // 8*64 floats
#define SMEM_TOTAL (OFF_CNT + 2048)

__device__ __align__(16) unsigned char g_x[(size_t)NT_MAX * 65536]; // per tile: Xh 32K | Xl 32K, swizzled
__device__ __align__(16) unsigned char g_mu[32768];                 // MuH 16K | MuL 16K, swizzled
__device__ float g_pmean[NB * K * D];
__device__ float g_pcnt[NB * K];
__device__ float g_mean[K * D];

__device__ __forceinline__ uint32_t smem_u32(const void* p) {
    uint32_t a;
    asm("{ .reg .u64 t; cvta.to.shared.u64 t, %1; cvt.u32.u64 %0, t; }" : "=r"(a) : "l"(p));
    return a;
}
__device__ __forceinline__ void ldsm_x4(uint32_t* r, uint32_t a) {
    asm volatile("ldmatrix.sync.aligned.m8n8.x4.shared.b16 {%0,%1,%2,%3}, [%4];"
        : "=r"(r[0]), "=r"(r[1]), "=r"(r[2]), "=r"(r[3]) : "r"(a));
}
__device__ __forceinline__ void ldsm_x4t(uint32_t* r, uint32_t a) {
    asm volatile("ldmatrix.sync.aligned.m8n8.x4.trans.shared.b16 {%0,%1,%2,%3}, [%4];"
        : "=r"(r[0]), "=r"(r[1]), "=r"(r[2]), "=r"(r[3]) : "r"(a));
}
__device__ __forceinline__ void mma_bf16(float* c, const uint32_t* a, const uint32_t* b) {
    asm volatile("mma.sync.aligned.m16n8k16.row.col.f32.bf16.bf16.f32 "
        "{%0,%1,%2,%3}, {%4,%5,%6,%7}, {%8,%9}, {%0,%1,%2,%3};"
        : "+f"(c[0]), "+f"(c[1]), "+f"(c[2]), "+f"(c[3])
        : "r"(a[0]), "r"(a[1]), "r"(a[2]), "r"(a[3]), "r"(b[0]), "r"(b[1]));
}
__device__ __forceinline__ void cp16(uint32_t dst, const void* src) {
    asm volatile("cp.async.cg.shared.global [%0], [%1], 16;" :: "r"(dst), "l"(src) : "memory");
}
#define CP_COMMIT() asm volatile("cp.async.commit_group;" ::: "memory")
#define CP_WAIT0()  asm volatile("cp.async.wait_group 0;" ::: "memory")

__device__ __forceinline__ uint32_t pack_bf16x2(__nv_bfloat16 a, __nv_bfloat16 b) {
    __nv_bfloat162 v(a, b);
    return *(uint32_t*)&v;
}

// FMA-pipe exp(TEMP * x): magic-number range reduction + degree-5 2^f poly.
// |TEMP*x| <= ~31, abs poly err ~2e-6. No MUFU.
__device__ __forceinline__ float fexp30(float x) {
    const float ZS = 43.28085122666891f;        // 30 * log2(e)
    const float MAGIC = 12582912.0f;            // 1.5 * 2^23
    float z  = x * ZS;
    float zj = z + MAGIC;                       // round-to-nearest int in low bits
    float f  = z - (zj - MAGIC);                // f in [-0.5, 0.5]
    int bits = __float_as_int(zj);
    float p = 0.0013333558146428443f;
    p = fmaf(p, f, 0.009618129842071803f);
    p = fmaf(p, f, 0.05550410866482158f);
    p = fmaf(p, f, 0.2402265069591007f);
    p = fmaf(p, f, 0.6931471805599453f);
    p = fmaf(p, f, 1.0f);
    return p * __int_as_float((bits << 23) + 0x3F800000);
}

// ---------------------------------------------------------------------------
__global__ void prep_kernel(const float* __restrict__ x, int N, int rowsPad) {
    int w = (blockIdx.x * blockDim.x + threadIdx.x) >> 5;
    int lane = threadIdx.x & 31;
    if (w >= rowsPad) return;
    float4 v = make_float4(0.f, 0.f, 0.f, 0.f);
    if (w < N) {
        v = ((const float4*)(x + (size_t)w * D))[lane];
        float ss = v.x*v.x + v.y*v.y + v.z*v.z + v.w*v.w;
        #pragma unroll
        for (int o = 16; o > 0; o >>= 1) ss += __shfl_xor_sync(0xffffffffu, ss, o);
        float inv = 1.0f / (sqrtf(ss) + EPSn);
        v.x *= inv; v.y *= inv; v.z *= inv; v.w *= inv;
    }
    float f[4] = {v.x, v.y, v.z, v.w};
    __nv_bfloat16 h[4], lo[4];
    #pragma unroll
    for (int i = 0; i < 4; i++) {
        h[i]  = __float2bfloat16(f[i]);
        lo[i] = __float2bfloat16(f[i] - __bfloat162float(h[i]));
    }
    uint2 uh, ul;
    uh.x = pack_bf16x2(h[0], h[1]);  uh.y = pack_bf16x2(h[2], h[3]);
    ul.x = pack_bf16x2(lo[0], lo[1]); ul.y = pack_bf16x2(lo[2], lo[3]);
    int t = w >> 7, rl = w & 127, d0 = lane * 4;
    uint32_t off = (uint32_t)rl * 256 + ((((d0 >> 3) ^ (rl & 7)) & 15) << 4) + ((d0 & 7) << 1);
    unsigned char* base = g_x + (size_t)t * 65536;
    *(uint2*)(base + off)         = uh;
    *(uint2*)(base + 32768 + off) = ul;
}

// ---------------------------------------------------------------------------
__device__ __forceinline__ void write_mu(int k, int d, float nv) {
    __nv_bfloat16 h = __float2bfloat16(nv);
    __nv_bfloat16 l = __float2bfloat16(nv - __bfloat162float(h));
    uint32_t off = (uint32_t)k * 256 + ((((d >> 3) ^ (k & 7)) & 15) << 4) + ((d & 7) << 1);
    *(__nv_bfloat16*)(g_mu + off)         = h;
    *(__nv_bfloat16*)(g_mu + 16384 + off) = l;
}

__global__ void init_mu_kernel(const float* __restrict__ init) {
    int k = blockIdx.x, d = threadIdx.x;
    float v = init[k * D + d];
    __shared__ float sred[4];
    float ss = v * v;
    #pragma unroll
    for (int o = 16; o > 0; o >>= 1) ss += __shfl_xor_sync(0xffffffffu, ss, o);
    if ((d & 31) == 0) sred[d >> 5] = ss;
    __syncthreads();
    float tot = sred[0] + sred[1] + sred[2] + sred[3];
    write_mu(k, d, v / (sqrtf(tot) + EPSn));
}

// ---------------------------------------------------------------------------
__global__ void reduce_mean_kernel() {
    int gidx = blockIdx.x * 256 + threadIdx.x;   // 65536 threads
    int i = gidx >> 3, part = gidx & 7;
    const float* p = g_pmean + i;
    float s = 0.0f;
    #pragma unroll
    for (int j = 0; j < 18; j++)
        s += p[(size_t)(part + j * 8) * (K * D)];
    if (part < NB - 144)
        s += p[(size_t)(part + 144) * (K * D)];
    s += __shfl_xor_sync(0xffffffffu, s, 1);
    s += __shfl_xor_sync(0xffffffffu, s, 2);
    s += __shfl_xor_sync(0xffffffffu, s, 4);
    if (part == 0) g_mean[i] = s;
}

__global__ void update_kernel(int last, float* __restrict__ mu_out) {
    int k = blockIdx.x, d = threadIdx.x;
    __shared__ float swred[4];
    __shared__ float sred[4];
    float c = 0.0f;
    for (int b = d; b < NB; b += 128) c += g_pcnt[b * K + k];
    #pragma unroll
    for (int o = 16; o > 0; o >>= 1) c += __shfl_xor_sync(0xffffffffu, c, o);
    if ((d & 31) == 0) swred[d >> 5] = c;
    __syncthreads();
    float cs = swred[0] + swred[1] + swred[2] + swred[3];
    float v = g_mean[k * D + d] / cs;
    float ss = v * v;
    #pragma unroll
    for (int o = 16; o > 0; o >>= 1) ss += __shfl_xor_sync(0xffffffffu, ss, o);
    if ((d & 31) == 0) sred[d >> 5] = ss;
    __syncthreads();
    float tot = sred[0] + sred[1] + sred[2] + sred[3];
    if (last) mu_out[k * D + d] = v;
    else      write_mu(k, d, v / (sqrtf(tot) + EPSn));
}

// ---------------------------------------------------------------------------
template<bool LAST>
__global__ void __launch_bounds__(256, 1) iter_kernel(float* __restrict__ r_out,
                                                      int N, int nT) {
    extern __shared__ unsigned char sm[];
    int tid = threadIdx.x, w = tid >> 5, lane = tid & 31;
    int bid = blockIdx.x;
    int t0 = (int)((long long)bid * nT / gridDim.x);
    int t1 = (int)((long long)(bid + 1) * nT / gridDim.x);
    float* gp = g_pmean + (size_t)bid * K * D;
    if (t0 >= t1) {
        for (int i = tid; i < K * D; i += 256) gp[i] = 0.0f;
        if (tid < K) g_pcnt[bid * K + tid] = 0.0f;
        return;
    }
    uint32_t sb = smem_u32(sm);
    uint32_t sMuH = sb + OFF_MU;
    uint32_t sR   = sb + OFF_R;
    float* scnt = (float*)(sm + OFF_CNT);

    // stage Mu (32KB) + X(t0) (64KB)
    #pragma unroll
    for (int j = 0; j < 8; j++)
        cp16(sMuH + (tid + 256 * j) * 16, g_mu + (tid + 256 * j) * 16);
    {
        const unsigned char* gx = g_x + (size_t)t0 * 65536;
        #pragma unroll
        for (int j = 0; j < 16; j++)
            cp16(sb + OFF_X + (tid + 256 * j) * 16, gx + (tid + 256 * j) * 16);
    }
    CP_COMMIT(); CP_WAIT0();
    __syncthreads();

    float C2[8][4];
    #pragma unroll
    for (int f = 0; f < 8; f++)
        #pragma unroll
        for (int q = 0; q < 4; q++) C2[f][q] = 0.0f;
    float cacc[16];
    #pragma unroll
    for (int j = 0; j < 16; j++) cacc[j] = 0.0f;

    int m0  = w * 16;                       // GEMM1 row strip
    int kc0 = (w & 3) * 16;                 // GEMM2 cluster strip
    int db  = (w >> 2) * 64;                // GEMM2 d half
    int g = lane >> 2, j2 = lane & 3;

    for (int t = t0; t < t1; t++) {
        int buf = (t - t0) & 1;
        uint32_t sX = sb + OFF_X + buf * 65536;       // Xh; Xl at +32768
        if (t + 1 < t1) {
            const unsigned char* gx = g_x + (size_t)(t + 1) * 65536;
            uint32_t dst = sb + OFF_X + (buf ^ 1) * 65536;
            #pragma unroll
            for (int j = 0; j < 16; j++)
                cp16(dst + (tid + 256 * j) * 16, gx + (tid + 256 * j) * 16);
        }
        CP_COMMIT();

        // ---- GEMM1: C1[16 rows x 64 kc] = X . Mu^T (3-term split) ----
        float C1[8][4];
        #pragma unroll
        for (int f = 0; f < 8; f++)
            #pragma unroll
            for (int q = 0; q < 4; q++) C1[f][q] = 0.0f;
        #pragma unroll
        for (int ks = 0; ks < 8; ks++) {
            uint32_t ah[4], al[4];
            int ar = m0 + (lane & 15);
            int ac = ks * 16 + ((lane >> 4) << 3);
            uint32_t aaddr = sX + (uint32_t)ar * 256 + ((((ac >> 3) ^ (ar & 7)) & 15) << 4);
            ldsm_x4(ah, aaddr);
            ldsm_x4(al, aaddr + 32768);
            #pragma unroll
            for (int fp = 0; fp < 4; fp++) {
                int brow = 16 * fp + ((lane >> 4) << 3) + (lane & 7);
                int bc = ks * 16 + (((lane >> 3) & 1) << 3);
                uint32_t baddr = sMuH + (uint32_t)brow * 256 + ((((bc >> 3) ^ (brow & 7)) & 15) << 4);
                uint32_t bh4[4], bl4[4];
                ldsm_x4(bh4, baddr);
                ldsm_x4(bl4, baddr + 16384);
                mma_bf16(C1[2*fp],   ah, bh4);
                mma_bf16(C1[2*fp],   al, bh4);
                mma_bf16(C1[2*fp],   ah, bl4);
                mma_bf16(C1[2*fp+1], ah, bh4 + 2);
                mma_bf16(C1[2*fp+1], al, bh4 + 2);
                mma_bf16(C1[2*fp+1], ah, bl4 + 2);
            }
        }

        // ---- softmax (max-free; |logit| <= ~30), exp on FMA pipe ----
        int grow0 = t * TILE + m0 + g;
        int grow1 = grow0 + 8;
        float s0 = 0.0f, s1 = 0.0f;
        #pragma unroll
        for (int f = 0; f < 8; f++) {
            #pragma unroll
            for (int q = 0; q < 4; q++) C1[f][q] = fexp30(C1[f][q]);
            s0 += C1[f][0] + C1[f][1];
            s1 += C1[f][2] + C1[f][3];
        }
        s0 += __shfl_xor_sync(0xffffffffu, s0, 1); s0 += __shfl_xor_sync(0xffffffffu, s0, 2);
        s1 += __shfl_xor_sync(0xffffffffu, s1, 1); s1 += __shfl_xor_sync(0xffffffffu, s1, 2);
        float inv0 = (grow0 < N) ? 1.0f / s0 : 0.0f;
        float inv1 = (grow1 < N) ? 1.0f / s1 : 0.0f;
        int row0 = m0 + g, row1 = row0 + 8;
        #pragma unroll
        for (int f = 0; f < 8; f++) {
            float r0a = C1[f][0] * inv0, r0b = C1[f][1] * inv0;
            float r1a = C1[f][2] * inv1, r1b = C1[f][3] * inv1;
            cacc[2*f]   += r0a + r1a;
            cacc[2*f+1] += r0b + r1b;
            int kc = 8 * f + 2 * j2;
            {
                __nv_bfloat16 ha = __float2bfloat16(r0a), hb = __float2bfloat16(r0b);
                __nv_bfloat16 la = __float2bfloat16(r0a - __bfloat162float(ha));
                __nv_bfloat16 lb = __float2bfloat16(r0b - __bfloat162float(hb));
                uint32_t off = (uint32_t)row0 * 128 + (((f ^ (row0 & 7)) & 7) << 4) + (j2 << 2);
                *(uint32_t*)(sm + OFF_R + off)         = pack_bf16x2(ha, hb);
                *(uint32_t*)(sm + OFF_R + 16384 + off) = pack_bf16x2(la, lb);
            }
            {
                __nv_bfloat16 ha = __float2bfloat16(r1a), hb = __float2bfloat16(r1b);
                __nv_bfloat16 la = __float2bfloat16(r1a - __bfloat162float(ha));
                __nv_bfloat16 lb = __float2bfloat16(r1b - __bfloat162float(hb));
                uint32_t off = (uint32_t)row1 * 128 + (((f ^ (row1 & 7)) & 7) << 4) + (j2 << 2);
                *(uint32_t*)(sm + OFF_R + off)         = pack_bf16x2(ha, hb);
                *(uint32_t*)(sm + OFF_R + 16384 + off) = pack_bf16x2(la, lb);
            }
            if (LAST) {
                if (grow0 < N) *(float2*)(r_out + (size_t)grow0 * K + kc) = make_float2(r0a, r0b);
                if (grow1 < N) *(float2*)(r_out + (size_t)grow1 * K + kc) = make_float2(r1a, r1b);
            }
        }
        __syncthreads();

        // ---- GEMM2: C2[16 kc x 64 d] += R^T . X (3-term split) ----
        #pragma unroll
        for (int ks = 0; ks < 8; ks++) {
            int row0k = ks * 16;
            uint32_t ah[4], al[4];
            int arm = row0k + (lane & 7) + ((lane >> 4) << 3);
            int acm = kc0 + ((lane >> 3) & 1) * 8;
            uint32_t aaddr = sR + (uint32_t)arm * 128 + ((((acm >> 3) ^ (arm & 7)) & 7) << 4);
            ldsm_x4t(ah, aaddr);
            ldsm_x4t(al, aaddr + 16384);
            #pragma unroll
            for (int fp = 0; fp < 4; fp++) {
                int brm = row0k + (((lane >> 3) & 1) << 3) + (lane & 7);
                int d0c = db + 16 * fp + ((lane >> 4) << 3);
                uint32_t baddr = sX + (uint32_t)brm * 256 + ((((d0c >> 3) ^ (brm & 7)) & 15) << 4);
                uint32_t bh4[4], bl4[4];
                ldsm_x4t(bh4, baddr);
                ldsm_x4t(bl4, baddr + 32768);
                mma_bf16(C2[2*fp],   ah, bh4);
                mma_bf16(C2[2*fp],   al, bh4);
                mma_bf16(C2[2*fp],   ah, bl4);
                mma_bf16(C2[2*fp+1], ah, bh4 + 2);
                mma_bf16(C2[2*fp+1], al, bh4 + 2);
                mma_bf16(C2[2*fp+1], ah, bl4 + 2);
            }
        }
        CP_WAIT0();
        __syncthreads();
    }

    // ---- epilogue: counts ----
    #pragma unroll
    for (int j = 0; j < 16; j++) {
        cacc[j] += __shfl_xor_sync(0xffffffffu, cacc[j], 4);
        cacc[j] += __shfl_xor_sync(0xffffffffu, cacc[j], 8);
        cacc[j] += __shfl_xor_sync(0xffffffffu, cacc[j], 16);
    }
    if (lane < 4) {
        #pragma unroll
        for (int f = 0; f < 8; f++) {
            scnt[w * 64 + 8 * f + 2 * lane]     = cacc[2*f];
            scnt[w * 64 + 8 * f + 2 * lane + 1] = cacc[2*f+1];
        }
    }
    __syncthreads();
    if (tid < K) {
        float c = 0.0f;
        #pragma unroll
        for (int ww = 0; ww < 8; ww++) c += scnt[ww * 64 + tid];
        g_pcnt[bid * K + tid] = c;
    }
    // ---- epilogue: mean partials ----
    #pragma unroll
    for (int f = 0; f < 8; f++) {
        int d0 = db + 8 * f + 2 * j2;
        *(float2*)(gp + (kc0 + g) * D + d0)     = make_float2(C2[f][0], C2[f][1]);
        *(float2*)(gp + (kc0 + g + 8) * D + d0) = make_float2(C2[f][2], C2[f][3]);
    }
}

// ---------------------------------------------------------------------------
extern "C" void kernel_launch(void* const* d_in, const int* in_sizes, int n_in,
                              void* d_out, int out_size) {
    const float* embeds = (const float*)d_in[0];
    const float* init   = (const float*)d_in[1];
    int N = in_sizes[0] / D;
    int nT = (N + TILE - 1) / TILE;
    if (nT > NT_MAX) nT = NT_MAX;
    float* out_mu = (float*)d_out;
    float* out_r  = (float*)d_out + K * D;

    cudaFuncSetAttribute(iter_kernel<false>, cudaFuncAttributeMaxDynamicSharedMemorySize, SMEM_TOTAL);
    cudaFuncSetAttribute(iter_kernel<true>,  cudaFuncAttributeMaxDynamicSharedMemorySize, SMEM_TOTAL);

    int rowsPad = nT * TILE;
    prep_kernel<<<(rowsPad + 7) / 8, 256>>>(embeds, N, rowsPad);
    init_mu_kernel<<<K, 128>>>(init);

    for (int it = 0; it < ITERS; it++) {
        int last = (it == ITERS - 1);
        if (last) iter_kernel<true><<<NB, 256, SMEM_TOTAL>>>(out_r, N, nT);
        else      iter_kernel<false><<<NB, 256, SMEM_TOTAL>>>(nullptr, N, nT);
        reduce_mean_kernel<<<256, 256>>>();
        update_kernel<<<K, 128>>>(last, out_mu);
    }
}

// round 9
// speedup vs baseline: 1.0188x; 1.0188x over previous
#include <cuda_runtime.h>
#include <cuda_bf16.h>
#include <cstdint>

#define D 128
#define K 64
#define TILE 64
#define NT_MAX 3125
#define NBLK 296
#define TEMP 30.0f
#define EPSn 1e-6f
#define ITERS 11

// smem byte offsets (per CTA: 113 KB -> 2 CTAs/SM)
#define OFF_MU 0                 // MuH 16KB | MuL 16KB
#define OFF_X  32768             // buf0: Xh 16K | Xl 16K ; buf1 at +32768
#define OFF_R  98304             // Rh 8K | Rl 8K
#define OFF_CNT 114688           // 4*64 floats
#define SMEM_TOTAL (OFF_CNT + 1024)

__device__ __align__(16) unsigned char g_x[(size_t)NT_MAX * 32768]; // per 64-row tile: Xh 16K | Xl 16K, swizzled
__device__ __align__(16) unsigned char g_mu[32768];                 // MuH 16K | MuL 16K, swizzled
__device__ float g_pmean[NBLK * K * D];
__device__ float g_pcnt[NBLK * K];
__device__ float g_mean[K * D];

__device__ __forceinline__ uint32_t smem_u32(const void* p) {
    uint32_t a;
    asm("{ .reg .u64 t; cvta.to.shared.u64 t, %1; cvt.u32.u64 %0, t; }" : "=r"(a) : "l"(p));
    return a;
}
__device__ __forceinline__ void ldsm_x4(uint32_t* r, uint32_t a) {
    asm volatile("ldmatrix.sync.aligned.m8n8.x4.shared.b16 {%0,%1,%2,%3}, [%4];"
        : "=r"(r[0]), "=r"(r[1]), "=r"(r[2]), "=r"(r[3]) : "r"(a));
}
__device__ __forceinline__ void ldsm_x4t(uint32_t* r, uint32_t a) {
    asm volatile("ldmatrix.sync.aligned.m8n8.x4.trans.shared.b16 {%0,%1,%2,%3}, [%4];"
        : "=r"(r[0]), "=r"(r[1]), "=r"(r[2]), "=r"(r[3]) : "r"(a));
}
__device__ __forceinline__ void mma_bf16(float* c, const uint32_t* a, const uint32_t* b) {
    asm volatile("mma.sync.aligned.m16n8k16.row.col.f32.bf16.bf16.f32 "
        "{%0,%1,%2,%3}, {%4,%5,%6,%7}, {%8,%9}, {%0,%1,%2,%3};"
        : "+f"(c[0]), "+f"(c[1]), "+f"(c[2]), "+f"(c[3])
        : "r"(a[0]), "r"(a[1]), "r"(a[2]), "r"(a[3]), "r"(b[0]), "r"(b[1]));
}
__device__ __forceinline__ void cp16(uint32_t dst, const void* src) {
    asm volatile("cp.async.cg.shared.global [%0], [%1], 16;" :: "r"(dst), "l"(src) : "memory");
}
#define CP_COMMIT() asm volatile("cp.async.commit_group;" ::: "memory")
#define CP_WAIT0()  asm volatile("cp.async.wait_group 0;" ::: "memory")

__device__ __forceinline__ uint32_t pack_bf16x2(__nv_bfloat16 a, __nv_bfloat16 b) {
    __nv_bfloat162 v(a, b);
    return *(uint32_t*)&v;
}

// ---------------------------------------------------------------------------
// prep: normalize rows, split fp32->bf16 hi/lo, write swizzled 64-row tiles
__global__ void prep_kernel(const float* __restrict__ x, int N, int rowsPad) {
    int w = (blockIdx.x * blockDim.x + threadIdx.x) >> 5;
    int lane = threadIdx.x & 31;
    if (w >= rowsPad) return;
    float4 v = make_float4(0.f, 0.f, 0.f, 0.f);
    if (w < N) {
        v = ((const float4*)(x + (size_t)w * D))[lane];
        float ss = v.x*v.x + v.y*v.y + v.z*v.z + v.w*v.w;
        #pragma unroll
        for (int o = 16; o > 0; o >>= 1) ss += __shfl_xor_sync(0xffffffffu, ss, o);
        float inv = 1.0f / (sqrtf(ss) + EPSn);
        v.x *= inv; v.y *= inv; v.z *= inv; v.w *= inv;
    }
    float f[4] = {v.x, v.y, v.z, v.w};
    __nv_bfloat16 h[4], lo[4];
    #pragma unroll
    for (int i = 0; i < 4; i++) {
        h[i]  = __float2bfloat16(f[i]);
        lo[i] = __float2bfloat16(f[i] - __bfloat162float(h[i]));
    }
    uint2 uh, ul;
    uh.x = pack_bf16x2(h[0], h[1]);  uh.y = pack_bf16x2(h[2], h[3]);
    ul.x = pack_bf16x2(lo[0], lo[1]); ul.y = pack_bf16x2(lo[2], lo[3]);
    int t = w >> 6, rl = w & 63, d0 = lane * 4;
    uint32_t off = (uint32_t)rl * 256 + ((((d0 >> 3) ^ (rl & 7)) & 15) << 4) + ((d0 & 7) << 1);
    unsigned char* base = g_x + (size_t)t * 32768;
    *(uint2*)(base + off)         = uh;
    *(uint2*)(base + 16384 + off) = ul;
}

// ---------------------------------------------------------------------------
__device__ __forceinline__ void write_mu(int k, int d, float nv) {
    __nv_bfloat16 h = __float2bfloat16(nv);
    __nv_bfloat16 l = __float2bfloat16(nv - __bfloat162float(h));
    uint32_t off = (uint32_t)k * 256 + ((((d >> 3) ^ (k & 7)) & 15) << 4) + ((d & 7) << 1);
    *(__nv_bfloat16*)(g_mu + off)         = h;
    *(__nv_bfloat16*)(g_mu + 16384 + off) = l;
}

__global__ void init_mu_kernel(const float* __restrict__ init) {
    int k = blockIdx.x, d = threadIdx.x;
    float v = init[k * D + d];
    __shared__ float sred[4];
    float ss = v * v;
    #pragma unroll
    for (int o = 16; o > 0; o >>= 1) ss += __shfl_xor_sync(0xffffffffu, ss, o);
    if ((d & 31) == 0) sred[d >> 5] = ss;
    __syncthreads();
    float tot = sred[0] + sred[1] + sred[2] + sred[3];
    write_mu(k, d, v / (sqrtf(tot) + EPSn));
}

// ---------------------------------------------------------------------------
__global__ void reduce_mean_kernel() {
    int gidx = blockIdx.x * 256 + threadIdx.x;   // 65536 threads
    int i = gidx >> 3, part = gidx & 7;
    const float* p = g_pmean + i;
    float s = 0.0f;
    #pragma unroll
    for (int j = 0; j < 37; j++)                 // 8 * 37 = 296 exact
        s += p[(size_t)(part + j * 8) * (K * D)];
    s += __shfl_xor_sync(0xffffffffu, s, 1);
    s += __shfl_xor_sync(0xffffffffu, s, 2);
    s += __shfl_xor_sync(0xffffffffu, s, 4);
    if (part == 0) g_mean[i] = s;
}

__global__ void update_kernel(int last, float* __restrict__ mu_out) {
    int k = blockIdx.x, d = threadIdx.x;
    __shared__ float swred[4];
    __shared__ float sred[4];
    float c = 0.0f;
    for (int b = d; b < NBLK; b += 128) c += g_pcnt[b * K + k];
    #pragma unroll
    for (int o = 16; o > 0; o >>= 1) c += __shfl_xor_sync(0xffffffffu, c, o);
    if ((d & 31) == 0) swred[d >> 5] = c;
    __syncthreads();
    float cs = swred[0] + swred[1] + swred[2] + swred[3];
    float v = g_mean[k * D + d] / cs;
    float ss = v * v;
    #pragma unroll
    for (int o = 16; o > 0; o >>= 1) ss += __shfl_xor_sync(0xffffffffu, ss, o);
    if ((d & 31) == 0) sred[d >> 5] = ss;
    __syncthreads();
    float tot = sred[0] + sred[1] + sred[2] + sred[3];
    if (last) mu_out[k * D + d] = v;
    else      write_mu(k, d, v / (sqrtf(tot) + EPSn));
}

// ---------------------------------------------------------------------------
// 128 threads (4 warps), 2 CTAs/SM. TILE = 64 rows.
template<bool LAST>
__global__ void __launch_bounds__(128, 2) iter_kernel(float* __restrict__ r_out,
                                                      int N, int nT) {
    extern __shared__ unsigned char sm[];
    int tid = threadIdx.x, w = tid >> 5, lane = tid & 31;
    int bid = blockIdx.x;
    int t0 = (int)((long long)bid * nT / gridDim.x);
    int t1 = (int)((long long)(bid + 1) * nT / gridDim.x);
    float* gp = g_pmean + (size_t)bid * K * D;
    if (t0 >= t1) {
        for (int i = tid; i < K * D; i += 128) gp[i] = 0.0f;
        if (tid < K) g_pcnt[bid * K + tid] = 0.0f;
        return;
    }
    uint32_t sb = smem_u32(sm);
    uint32_t sMuH = sb + OFF_MU;
    uint32_t sR   = sb + OFF_R;
    float* scnt = (float*)(sm + OFF_CNT);

    // stage Mu (32KB) + X(t0) (32KB)
    #pragma unroll
    for (int j = 0; j < 16; j++)
        cp16(sMuH + (tid + 128 * j) * 16, g_mu + (tid + 128 * j) * 16);
    {
        const unsigned char* gx = g_x + (size_t)t0 * 32768;
        #pragma unroll
        for (int j = 0; j < 16; j++)
            cp16(sb + OFF_X + (tid + 128 * j) * 16, gx + (tid + 128 * j) * 16);
    }
    CP_COMMIT(); CP_WAIT0();
    __syncthreads();

    float C2[16][4];
    #pragma unroll
    for (int f = 0; f < 16; f++)
        #pragma unroll
        for (int q = 0; q < 4; q++) C2[f][q] = 0.0f;
    float cacc[16];
    #pragma unroll
    for (int j = 0; j < 16; j++) cacc[j] = 0.0f;

    int m0  = w * 16;                       // GEMM1 row strip (rows 0..63)
    int kc0 = w * 16;                       // GEMM2 cluster strip
    int g = lane >> 2, j2 = lane & 3;

    for (int t = t0; t < t1; t++) {
        int buf = (t - t0) & 1;
        uint32_t sX = sb + OFF_X + buf * 32768;       // Xh; Xl at +16384
        if (t + 1 < t1) {
            const unsigned char* gx = g_x + (size_t)(t + 1) * 32768;
            uint32_t dst = sb + OFF_X + (buf ^ 1) * 32768;
            #pragma unroll
            for (int j = 0; j < 16; j++)
                cp16(dst + (tid + 128 * j) * 16, gx + (tid + 128 * j) * 16);
        }
        CP_COMMIT();

        // ---- GEMM1: C1[16 rows x 64 kc] = X . Mu^T (3-term split) ----
        float C1[8][4];
        #pragma unroll
        for (int f = 0; f < 8; f++)
            #pragma unroll
            for (int q = 0; q < 4; q++) C1[f][q] = 0.0f;
        #pragma unroll
        for (int ks = 0; ks < 8; ks++) {
            uint32_t ah[4], al[4];
            int ar = m0 + (lane & 15);
            int ac = ks * 16 + ((lane >> 4) << 3);
            uint32_t aaddr = sX + (uint32_t)ar * 256 + ((((ac >> 3) ^ (ar & 7)) & 15) << 4);
            ldsm_x4(ah, aaddr);
            ldsm_x4(al, aaddr + 16384);
            #pragma unroll
            for (int fp = 0; fp < 4; fp++) {
                int brow = 16 * fp + ((lane >> 4) << 3) + (lane & 7);
                int bc = ks * 16 + (((lane >> 3) & 1) << 3);
                uint32_t baddr = sMuH + (uint32_t)brow * 256 + ((((bc >> 3) ^ (brow & 7)) & 15) << 4);
                uint32_t bh4[4], bl4[4];
                ldsm_x4(bh4, baddr);
                ldsm_x4(bl4, baddr + 16384);
                mma_bf16(C1[2*fp],   ah, bh4);
                mma_bf16(C1[2*fp],   al, bh4);
                mma_bf16(C1[2*fp],   ah, bl4);
                mma_bf16(C1[2*fp+1], ah, bh4 + 2);
                mma_bf16(C1[2*fp+1], al, bh4 + 2);
                mma_bf16(C1[2*fp+1], ah, bl4 + 2);
            }
        }

        // ---- softmax (max-free; |logit| <= ~30) ----
        int grow0 = t * TILE + m0 + g;
        int grow1 = grow0 + 8;
        float s0 = 0.0f, s1 = 0.0f;
        #pragma unroll
        for (int f = 0; f < 8; f++) {
            #pragma unroll
            for (int q = 0; q < 4; q++) C1[f][q] = __expf(TEMP * C1[f][q]);
            s0 += C1[f][0] + C1[f][1];
            s1 += C1[f][2] + C1[f][3];
        }
        s0 += __shfl_xor_sync(0xffffffffu, s0, 1); s0 += __shfl_xor_sync(0xffffffffu, s0, 2);
        s1 += __shfl_xor_sync(0xffffffffu, s1, 1); s1 += __shfl_xor_sync(0xffffffffu, s1, 2);
        float inv0 = (grow0 < N) ? 1.0f / s0 : 0.0f;
        float inv1 = (grow1 < N) ? 1.0f / s1 : 0.0f;
        int row0 = m0 + g, row1 = row0 + 8;
        #pragma unroll
        for (int f = 0; f < 8; f++) {
            float r0a = C1[f][0] * inv0, r0b = C1[f][1] * inv0;
            float r1a = C1[f][2] * inv1, r1b = C1[f][3] * inv1;
            cacc[2*f]   += r0a + r1a;
            cacc[2*f+1] += r0b + r1b;
            int kc = 8 * f + 2 * j2;
            {
                __nv_bfloat16 ha = __float2bfloat16(r0a), hb = __float2bfloat16(r0b);
                __nv_bfloat16 la = __float2bfloat16(r0a - __bfloat162float(ha));
                __nv_bfloat16 lb = __float2bfloat16(r0b - __bfloat162float(hb));
                uint32_t off = (uint32_t)row0 * 128 + (((f ^ (row0 & 7)) & 7) << 4) + (j2 << 2);
                *(uint32_t*)(sm + OFF_R + off)        = pack_bf16x2(ha, hb);
                *(uint32_t*)(sm + OFF_R + 8192 + off) = pack_bf16x2(la, lb);
            }
            {
                __nv_bfloat16 ha = __float2bfloat16(r1a), hb = __float2bfloat16(r1b);
                __nv_bfloat16 la = __float2bfloat16(r1a - __bfloat162float(ha));
                __nv_bfloat16 lb = __float2bfloat16(r1b - __bfloat162float(hb));
                uint32_t off = (uint32_t)row1 * 128 + (((f ^ (row1 & 7)) & 7) << 4) + (j2 << 2);
                *(uint32_t*)(sm + OFF_R + off)        = pack_bf16x2(ha, hb);
                *(uint32_t*)(sm + OFF_R + 8192 + off) = pack_bf16x2(la, lb);
            }
            if (LAST) {
                if (grow0 < N) *(float2*)(r_out + (size_t)grow0 * K + kc) = make_float2(r0a, r0b);
                if (grow1 < N) *(float2*)(r_out + (size_t)grow1 * K + kc) = make_float2(r1a, r1b);
            }
        }
        __syncthreads();

        // ---- GEMM2: C2[16 kc x 128 d] += R^T . X (3-term split), k = 64 rows ----
        #pragma unroll
        for (int ks = 0; ks < 4; ks++) {
            int row0k = ks * 16;
            uint32_t ah[4], al[4];
            int arm = row0k + (lane & 7) + ((lane >> 4) << 3);
            int acm = kc0 + ((lane >> 3) & 1) * 8;
            uint32_t aaddr = sR + (uint32_t)arm * 128 + ((((acm >> 3) ^ (arm & 7)) & 7) << 4);
            ldsm_x4t(ah, aaddr);
            ldsm_x4t(al, aaddr + 8192);
            #pragma unroll
            for (int fp = 0; fp < 8; fp++) {
                int brm = row0k + (((lane >> 3) & 1) << 3) + (lane & 7);
                int d0c = 16 * fp + ((lane >> 4) << 3);
                uint32_t baddr = sX + (uint32_t)brm * 256 + ((((d0c >> 3) ^ (brm & 7)) & 15) << 4);
                uint32_t bh4[4], bl4[4];
                ldsm_x4t(bh4, baddr);
                ldsm_x4t(bl4, baddr + 16384);
                mma_bf16(C2[2*fp],   ah, bh4);
                mma_bf16(C2[2*fp],   al, bh4);
                mma_bf16(C2[2*fp],   ah, bl4);
                mma_bf16(C2[2*fp+1], ah, bh4 + 2);
                mma_bf16(C2[2*fp+1], al, bh4 + 2);
                mma_bf16(C2[2*fp+1], ah, bl4 + 2);
            }
        }
        CP_WAIT0();
        __syncthreads();
    }

    // ---- epilogue: counts ----
    #pragma unroll
    for (int j = 0; j < 16; j++) {
        cacc[j] += __shfl_xor_sync(0xffffffffu, cacc[j], 4);
        cacc[j] += __shfl_xor_sync(0xffffffffu, cacc[j], 8);
        cacc[j] += __shfl_xor_sync(0xffffffffu, cacc[j], 16);
    }
    if (lane < 4) {
        #pragma unroll
        for (int f = 0; f < 8; f++) {
            scnt[w * 64 + 8 * f + 2 * lane]     = cacc[2*f];
            scnt[w * 64 + 8 * f + 2 * lane + 1] = cacc[2*f+1];
        }
    }
    __syncthreads();
    if (tid < K) {
        float c = scnt[tid] + scnt[64 + tid] + scnt[128 + tid] + scnt[192 + tid];
        g_pcnt[bid * K + tid] = c;
    }
    // ---- epilogue: mean partials ----
    #pragma unroll
    for (int f = 0; f < 16; f++) {
        int d0 = 8 * f + 2 * j2;
        *(float2*)(gp + (kc0 + g) * D + d0)     = make_float2(C2[f][0], C2[f][1]);
        *(float2*)(gp + (kc0 + g + 8) * D + d0) = make_float2(C2[f][2], C2[f][3]);
    }
}

// ---------------------------------------------------------------------------
extern "C" void kernel_launch(void* const* d_in, const int* in_sizes, int n_in,
                              void* d_out, int out_size) {
    const float* embeds = (const float*)d_in[0];
    const float* init   = (const float*)d_in[1];
    int N = in_sizes[0] / D;
    int nT = (N + TILE - 1) / TILE;
    if (nT > NT_MAX) nT = NT_MAX;
    float* out_mu = (float*)d_out;
    float* out_r  = (float*)d_out + K * D;

    cudaFuncSetAttribute(iter_kernel<false>, cudaFuncAttributeMaxDynamicSharedMemorySize, SMEM_TOTAL);
    cudaFuncSetAttribute(iter_kernel<true>,  cudaFuncAttributeMaxDynamicSharedMemorySize, SMEM_TOTAL);

    int rowsPad = nT * TILE;
    prep_kernel<<<(rowsPad + 7) / 8, 256>>>(embeds, N, rowsPad);
    init_mu_kernel<<<K, 128>>>(init);

    for (int it = 0; it < ITERS; it++) {
        int last = (it == ITERS - 1);
        if (last) iter_kernel<true><<<NBLK, 128, SMEM_TOTAL>>>(out_r, N, nT);
        else      iter_kernel<false><<<NBLK, 128, SMEM_TOTAL>>>(nullptr, N, nT);
        reduce_mean_kernel<<<256, 256>>>();
        update_kernel<<<K, 128>>>(last, out_mu);
    }
}